// round 5
// baseline (speedup 1.0000x reference)
#include <cuda_runtime.h>
#include <cuda_bf16.h>

// Problem constants
#define BB 4
#define NN 8192
#define PP 2048
#define CC 64
#define SS 32
#define NCH 68          // 3 xyz + 1 density + 64 features
#define WARPS_PER_BLK 4

// Scratch (device globals: allocation is forbidden)
__device__ float4 g_xyz4[BB * NN];                       // 512 KB, padded xyz
__device__ float  g_featT[(size_t)BB * NN * CC];         // 8 MB, features transposed to (B, N, C)

// ---------------------------------------------------------------------------
// Prep 1: xyz (B,N,3) -> float4 (B,N) for vectorized query loads
// ---------------------------------------------------------------------------
__global__ void prep_xyz_kernel(const float* __restrict__ xyz) {
    int i = blockIdx.x * blockDim.x + threadIdx.x;
    if (i < BB * NN) {
        float x = xyz[3 * i + 0];
        float y = xyz[3 * i + 1];
        float z = xyz[3 * i + 2];
        g_xyz4[i] = make_float4(x, y, z, 0.0f);
    }
}

// ---------------------------------------------------------------------------
// Prep 2: tiled transpose features (B,C,N) -> (B,N,C)
// grid: (N/32, C/32, B), block (32,8)
// ---------------------------------------------------------------------------
__global__ void prep_transpose_kernel(const float* __restrict__ feat) {
    __shared__ float tile[32][33];
    const int b  = blockIdx.z;
    const int c0 = blockIdx.y * 32;
    const int n0 = blockIdx.x * 32;
    const int tx = threadIdx.x;
    const int ty = threadIdx.y;

    const float* F = feat   + (size_t)b * CC * NN;
    float*       T = g_featT + (size_t)b * NN * CC;

#pragma unroll
    for (int k = 0; k < 32; k += 8)
        tile[ty + k][tx] = F[(size_t)(c0 + ty + k) * NN + (n0 + tx)];
    __syncthreads();
#pragma unroll
    for (int k = 0; k < 32; k += 8)
        T[(size_t)(n0 + ty + k) * CC + (c0 + tx)] = tile[tx][ty + k];
}

// ---------------------------------------------------------------------------
// Main: one warp per query point.
//   Phase 1: ellipsoid query with early exit (ballot + ordered append)
//   Phase 2: xyz + density channels, then staged feature gather
// ---------------------------------------------------------------------------
__global__ __launch_bounds__(32 * WARPS_PER_BLK)
void query_group_kernel(const float* __restrict__ new_xyz,
                        float* __restrict__ out) {
    __shared__ int   s_idx[WARPS_PER_BLK][SS];
    __shared__ float s_st[WARPS_PER_BLK][SS][65];   // padded: conflict-free transpose

    const int w    = threadIdx.x >> 5;
    const int lane = threadIdx.x & 31;
    const int q    = blockIdx.x * WARPS_PER_BLK + w;   // 0 .. B*P-1
    const int b    = q >> 11;                          // P = 2048
    const int p    = q & (PP - 1);

    const float nx = new_xyz[(size_t)(b * PP + p) * 3 + 0];
    const float ny = new_xyz[(size_t)(b * PP + p) * 3 + 1];
    const float nz = new_xyz[(size_t)(b * PP + p) * 3 + 2];

    const float4* __restrict__ X = g_xyz4 + b * NN;

    // ---- Phase 1: query. Must match reference bit-exactly:
    // q = 0; q += dx*dx*25.0f; q += dy*dy*6.25f; q += dz*dz*25.0f  (no FMA!)
    int count = 0;
    const unsigned lt_mask = (1u << lane) - 1u;
    for (int base = 0; base < NN; base += 32) {
        float4 pt = X[base + lane];
        float dx = __fsub_rn(nx, pt.x);
        float dy = __fsub_rn(ny, pt.y);
        float dz = __fsub_rn(nz, pt.z);
        float qx = __fmul_rn(__fmul_rn(dx, dx), 25.0f);
        float qy = __fmul_rn(__fmul_rn(dy, dy), 6.25f);
        float qz = __fmul_rn(__fmul_rn(dz, dz), 25.0f);
        float qv = __fadd_rn(__fadd_rn(qx, qy), qz);
        bool hit = (qv < 1.0f);
        unsigned m = __ballot_sync(0xffffffffu, hit);
        if (hit) {
            int pos = count + __popc(m & lt_mask);
            if (pos < SS) s_idx[w][pos] = base + lane;
        }
        count += __popc(m);
        if (count >= SS) break;   // uniform across warp
    }
    __syncwarp();

    const int cnt   = (count < SS) ? count : SS;
    const int first = (cnt > 0) ? s_idx[w][0] : 0;
    const int id    = (lane < cnt) ? s_idx[w][lane] : first;
    __syncwarp();

    // ---- Phase 2a: grouped_xyz (ch 0..2) + grouped_density (ch 3)
    float4 pt = X[id];
    float dx = pt.x - nx, dy = pt.y - ny, dz = pt.z - nz;
    float d2 = dx * dx + dy * dy + dz * dz;

    const size_t chan_stride = (size_t)PP * SS;
    const size_t ob = (((size_t)b * NCH) * PP + p) * SS + lane;  // lane == sample s
    out[ob + 0 * chan_stride] = pt.x;
    out[ob + 1 * chan_stride] = pt.y;
    out[ob + 2 * chan_stride] = pt.z;
    out[ob + 3 * chan_stride] = 0.25f * expf(50.0f * d2);

    // ---- Phase 2b: feature gather via smem staging.
    // Load: for each sample s, lanes read 64 contiguous channels (2x128B coalesced).
    // Store: lane = sample s, 64 coalesced 128B STGs across samples per channel.
    const float* __restrict__ FT = g_featT + (size_t)b * NN * CC;
#pragma unroll 8
    for (int s = 0; s < SS; s++) {
        int is = __shfl_sync(0xffffffffu, id, s);
        const float* row = FT + (size_t)is * CC;
        s_st[w][s][lane]      = row[lane];
        s_st[w][s][lane + 32] = row[lane + 32];
    }
    __syncwarp();

    float* of = out + ob + 4 * chan_stride;
#pragma unroll
    for (int c = 0; c < CC; c++)
        of[(size_t)c * chan_stride] = s_st[w][lane][c];
}

// ---------------------------------------------------------------------------
extern "C" void kernel_launch(void* const* d_in, const int* in_sizes, int n_in,
                              void* d_out, int out_size) {
    const float* xyz     = (const float*)d_in[0];   // (4, 8192, 3)
    const float* new_xyz = (const float*)d_in[1];   // (4, 2048, 3)
    const float* feat    = (const float*)d_in[2];   // (4, 64, 8192)
    float* out           = (float*)d_out;           // (4, 68, 2048, 32)

    prep_xyz_kernel<<<(BB * NN + 255) / 256, 256>>>(xyz);

    dim3 tb(32, 8);
    dim3 tg(NN / 32, CC / 32, BB);
    prep_transpose_kernel<<<tg, tb>>>(feat);

    query_group_kernel<<<(BB * PP) / WARPS_PER_BLK, 32 * WARPS_PER_BLK>>>(new_xyz, out);
}

// round 8
// speedup vs baseline: 1.7886x; 1.7886x over previous
#include <cuda_runtime.h>
#include <cuda_bf16.h>

// Problem constants
#define BB 4
#define NN 8192
#define PP 2048
#define CC 64
#define SS 32
#define NCH 68          // 3 xyz + 1 density + 64 features
#define WARPS_PER_BLK 4
#define SPAD 69         // 68 channels + 1 pad (69 = odd -> conflict-free strided access)

// Scratch (device globals: allocation is forbidden)
__device__ float4 g_xyz4[BB * NN];                       // 512 KB, padded xyz
__device__ float  g_featT[(size_t)BB * NN * CC];         // 8 MB, features transposed to (B, N, C)

// ---------------------------------------------------------------------------
// Fused prep: (a) xyz (B,N,3) -> float4, done by the y==0,z==0 block slice
//             (b) tiled transpose features (B,C,N) -> (B,N,C)
// grid: (N/32=256, C/32=2, B=4), block (32,8)
// ---------------------------------------------------------------------------
__global__ void prep_fused_kernel(const float* __restrict__ xyz,
                                  const float* __restrict__ feat) {
    __shared__ float tile[32][33];
    const int tx = threadIdx.x;
    const int ty = threadIdx.y;

    // (a) xyz packing: 256 blocks x 256 threads = 65536 >= 32768 items
    if (blockIdx.y == 0 && blockIdx.z == 0) {
        int i = blockIdx.x * 256 + ty * 32 + tx;
        if (i < BB * NN) {
            float x = xyz[3 * i + 0];
            float y = xyz[3 * i + 1];
            float z = xyz[3 * i + 2];
            g_xyz4[i] = make_float4(x, y, z, 0.0f);
        }
    }

    // (b) transpose tile
    const int b  = blockIdx.z;
    const int c0 = blockIdx.y * 32;
    const int n0 = blockIdx.x * 32;
    const float* F = feat    + (size_t)b * CC * NN;
    float*       T = g_featT + (size_t)b * NN * CC;

#pragma unroll
    for (int k = 0; k < 32; k += 8)
        tile[ty + k][tx] = F[(size_t)(c0 + ty + k) * NN + (n0 + tx)];
    __syncthreads();
#pragma unroll
    for (int k = 0; k < 32; k += 8)
        T[(size_t)(n0 + ty + k) * CC + (c0 + tx)] = tile[tx][ty + k];
}

// ---------------------------------------------------------------------------
// Main: one warp per query point.
//   Phase 1: ellipsoid query, 128 points/iter (MLP=4), early exit
//   Phase 2: stage all 68 channels in smem, vectorized STG.128 epilogue
// ---------------------------------------------------------------------------
__global__ __launch_bounds__(32 * WARPS_PER_BLK)
void query_group_kernel(const float* __restrict__ new_xyz,
                        float* __restrict__ out) {
    __shared__ int   s_idx[WARPS_PER_BLK][SS];
    __shared__ float s_st[WARPS_PER_BLK][SS][SPAD];  // [sample][channel], padded

    const int w    = threadIdx.x >> 5;
    const int lane = threadIdx.x & 31;
    const int q    = blockIdx.x * WARPS_PER_BLK + w;   // 0 .. B*P-1
    const int b    = q >> 11;                          // P = 2048
    const int p    = q & (PP - 1);

    const float nx = new_xyz[(size_t)(b * PP + p) * 3 + 0];
    const float ny = new_xyz[(size_t)(b * PP + p) * 3 + 1];
    const float nz = new_xyz[(size_t)(b * PP + p) * 3 + 2];

    const float4* __restrict__ X = g_xyz4 + b * NN;

    // ---- Phase 1: bit-exact vs reference (separately-rounded mul/mul/add,
    // inv_sq rounds to exactly {25.0f, 6.25f, 25.0f}). 128 points per
    // iteration: 4 independent LDG.128 per lane, then 4 ordered ballots.
    int count = 0;
    const unsigned lt_mask = (1u << lane) - 1u;
    for (int base = 0; base < NN && count < SS; base += 128) {
        float4 pts[4];
        pts[0] = X[base       + lane];
        pts[1] = X[base + 32  + lane];
        pts[2] = X[base + 64  + lane];
        pts[3] = X[base + 96  + lane];
#pragma unroll
        for (int j = 0; j < 4; j++) {
            float dx = __fsub_rn(nx, pts[j].x);
            float dy = __fsub_rn(ny, pts[j].y);
            float dz = __fsub_rn(nz, pts[j].z);
            float qx = __fmul_rn(__fmul_rn(dx, dx), 25.0f);
            float qy = __fmul_rn(__fmul_rn(dy, dy), 6.25f);
            float qz = __fmul_rn(__fmul_rn(dz, dz), 25.0f);
            float qv = __fadd_rn(__fadd_rn(qx, qy), qz);
            bool hit = (qv < 1.0f);
            unsigned m = __ballot_sync(0xffffffffu, hit);
            if (hit) {
                int pos = count + __popc(m & lt_mask);
                if (pos < SS) s_idx[w][pos] = base + 32 * j + lane;
            }
            count += __popc(m);
        }
    }
    __syncwarp();

    const int cnt   = (count < SS) ? count : SS;
    const int first = (cnt > 0) ? s_idx[w][0] : 0;
    const int id    = (lane < cnt) ? s_idx[w][lane] : first;
    __syncwarp();

    // ---- Phase 2a: stage xyz (ch 0..2) + density (ch 3). lane == sample s.
    float4 pt = X[id];
    float dx = pt.x - nx, dy = pt.y - ny, dz = pt.z - nz;
    float d2 = dx * dx + dy * dy + dz * dz;
    s_st[w][lane][0] = pt.x;
    s_st[w][lane][1] = pt.y;
    s_st[w][lane][2] = pt.z;
    s_st[w][lane][3] = 0.25f * expf(50.0f * d2);   // 1/density = 0.25*exp(d^2/(2*0.01))

    // ---- Phase 2b: feature gather into smem (ch 4..67).
    // Loads: per sample, 64 contiguous channels from (N,C) layout = 2x128B
    // coalesced, L2-resident (g_featT just written, fits in L2).
    const float* __restrict__ FT = g_featT + (size_t)b * NN * CC;
#pragma unroll 8
    for (int s = 0; s < SS; s++) {
        int is = __shfl_sync(0xffffffffu, id, s);
        const float* row = FT + (size_t)is * CC;
        s_st[w][s][4 + lane]      = row[lane];
        s_st[w][s][36 + lane]     = row[lane + 32];
    }
    __syncwarp();

    // ---- Epilogue: all 68 channels as STG.128, streaming (don't pollute L2).
    // lane = 8*cq + sq: channel-offset cq in 0..3, sample-quad sq in 0..7.
    // Conflict-free smem reads with SPAD=69.
    const int cq = lane >> 3;
    const int sq = lane & 7;
    const size_t chan_stride = (size_t)PP * SS;
    float* ob = out + (size_t)b * NCH * chan_stride + (size_t)p * SS;
#pragma unroll
    for (int c0 = 0; c0 < NCH; c0 += 4) {
        float4 v;
        v.x = s_st[w][4 * sq + 0][c0 + cq];
        v.y = s_st[w][4 * sq + 1][c0 + cq];
        v.z = s_st[w][4 * sq + 2][c0 + cq];
        v.w = s_st[w][4 * sq + 3][c0 + cq];
        __stcs((float4*)(ob + (size_t)(c0 + cq) * chan_stride + 4 * sq), v);
    }
}

// ---------------------------------------------------------------------------
extern "C" void kernel_launch(void* const* d_in, const int* in_sizes, int n_in,
                              void* d_out, int out_size) {
    const float* xyz     = (const float*)d_in[0];   // (4, 8192, 3)
    const float* new_xyz = (const float*)d_in[1];   // (4, 2048, 3)
    const float* feat    = (const float*)d_in[2];   // (4, 64, 8192)
    float* out           = (float*)d_out;           // (4, 68, 2048, 32)

    dim3 tb(32, 8);
    dim3 tg(NN / 32, CC / 32, BB);
    prep_fused_kernel<<<tg, tb>>>(xyz, feat);

    query_group_kernel<<<(BB * PP) / WARPS_PER_BLK, 32 * WARPS_PER_BLK>>>(new_xyz, out);
}